// round 9
// baseline (speedup 1.0000x reference)
#include <cuda_runtime.h>
#include <cuda_bf16.h>

// ---------------------------------------------------------------------------
// GridSample 3D, trilinear, zeros padding, align_corners=False
// input  [2, 32, 64, 64, 64] f32
// grid   [2, 96, 96, 96, 3]  f32
// output [2, 32, 96, 96, 96] f32
//
// R5 = R3 (fp32 channels-last scratch, float4 gathers) +
//   (a) per-location weight/offset precompute in shared (kills 8x redundant
//       coord ALU across the 8 channel-group lanes),
//   (b) packed fma.rn.f32x2 accumulation (halves fma-pipe issues).
// ---------------------------------------------------------------------------

#define NB   2
#define C    32
#define D    64
#define HH   64
#define W    64
#define S3   (D * HH * W)
#define DO   96
#define HO   96
#define WO   96

// channels-last scratch: [NB][S3][C] = 64 MiB
static __device__ float g_scratch[(size_t)NB * S3 * C];

// ---------------------------------------------------------------------------
// K1: [n][c][s] -> [n][s][c] transpose, 32x32 shared tile
// ---------------------------------------------------------------------------
__global__ void transpose_cl_kernel(const float* __restrict__ in) {
    __shared__ float tile[32][33];
    int bid   = blockIdx.x;
    int n     = bid >> 13;
    int sbase = (bid & 8191) << 5;
    int tx = threadIdx.x;
    int ty = threadIdx.y;

    const float* inp = in + (size_t)n * C * S3;
#pragma unroll
    for (int i = 0; i < 4; i++) {
        int c = ty + i * 8;
        tile[c][tx] = inp[(size_t)c * S3 + sbase + tx];
    }
    __syncthreads();
    float* dst = g_scratch + (size_t)n * S3 * C;
#pragma unroll
    for (int i = 0; i < 4; i++) {
        int s = ty + i * 8;
        dst[(size_t)(sbase + s) * C + tx] = tile[tx][s];
    }
}

// ---------------------------------------------------------------------------
// K2: sampler. 256 threads, 32 locations (one 32-wide x-strip).
// Phase A: warp 0 computes per-location corner weights + offsets -> shared.
// Phase B: loc = tid>>3, cg = tid&7: 8 float4 corner gathers, packed
//          f32x2 FMA accumulate, stage through stride-33 tile, coalesced out.
// grid: NB*DO*HO*(WO/32) = 55296 blocks.
// ---------------------------------------------------------------------------
__global__ __launch_bounds__(256) void sample_kernel(
    const float* __restrict__ grid, float* __restrict__ out) {
    __shared__ float gsh[96];            // 32 locations * (x,y,z)
    __shared__ float swgt[32 * 8];       // 8 corner weights per location
    __shared__ int   soff[32 * 4];       // base4, ox, oy, oz (float4 units)
    __shared__ float tile[32 * 33];      // [loc][chan], stride 33

    int bid = blockIdx.x;
    int xg  = bid % 3;  int t = bid / 3;
    int yo  = t % HO;   t /= HO;
    int zo  = t % DO;
    int n   = t / DO;

    int tid = threadIdx.x;

    long gbase = ((((long)n * DO + zo) * HO + yo) * WO + xg * 32) * 3;
    if (tid < 96) gsh[tid] = grid[gbase + tid];
    __syncthreads();

    // -------- Phase A: one thread per location --------
    if (tid < 32) {
        float gx = gsh[3 * tid + 0];
        float gy = gsh[3 * tid + 1];
        float gz = gsh[3 * tid + 2];

        // align_corners=False: (g+1)*32 - 0.5
        float ix = (gx + 1.0f) * 32.0f - 0.5f;
        float iy = (gy + 1.0f) * 32.0f - 0.5f;
        float iz = (gz + 1.0f) * 32.0f - 0.5f;

        float fx = floorf(ix), fy = floorf(iy), fz = floorf(iz);
        float tx = ix - fx, ty = iy - fy, tz = iz - fz;
        int x0 = (int)fx, y0 = (int)fy, z0 = (int)fz;
        int x1 = x0 + 1, y1 = y0 + 1, z1 = z0 + 1;

        float wx0 = (x0 >= 0 && x0 < W)  ? (1.0f - tx) : 0.0f;
        float wx1 = (x1 >= 0 && x1 < W)  ? tx          : 0.0f;
        float wy0 = (y0 >= 0 && y0 < HH) ? (1.0f - ty) : 0.0f;
        float wy1 = (y1 >= 0 && y1 < HH) ? ty          : 0.0f;
        float wz0 = (z0 >= 0 && z0 < D)  ? (1.0f - tz) : 0.0f;
        float wz1 = (z1 >= 0 && z1 < D)  ? tz          : 0.0f;

        int xc0 = min(max(x0, 0), W - 1),  xc1 = min(max(x1, 0), W - 1);
        int yc0 = min(max(y0, 0), HH - 1), yc1 = min(max(y1, 0), HH - 1);
        int zc0 = min(max(z0, 0), D - 1),  zc1 = min(max(z1, 0), D - 1);

        // offsets in float4 (16B) units; C floats = 8 float4
        int base4 = (((n * D + zc0) * HH + yc0) * W + xc0) * (C / 4);
        soff[tid * 4 + 0] = base4;
        soff[tid * 4 + 1] = (xc1 - xc0) * (C / 4);
        soff[tid * 4 + 2] = (yc1 - yc0) * (W * C / 4);
        soff[tid * 4 + 3] = (zc1 - zc0) * (HH * W * C / 4);

        float w00 = wz0 * wy0, w01 = wz0 * wy1;
        float w10 = wz1 * wy0, w11 = wz1 * wy1;
        swgt[tid * 8 + 0] = w00 * wx0;
        swgt[tid * 8 + 1] = w00 * wx1;
        swgt[tid * 8 + 2] = w01 * wx0;
        swgt[tid * 8 + 3] = w01 * wx1;
        swgt[tid * 8 + 4] = w10 * wx0;
        swgt[tid * 8 + 5] = w10 * wx1;
        swgt[tid * 8 + 6] = w11 * wx0;
        swgt[tid * 8 + 7] = w11 * wx1;
    }
    __syncthreads();

    // -------- Phase B: gather + packed accumulate --------
    int loc = tid >> 3;
    int cg  = tid & 7;

    int4 off = *reinterpret_cast<const int4*>(&soff[loc * 4]);   // base,ox,oy,oz
    float4 wA = *reinterpret_cast<const float4*>(&swgt[loc * 8]);
    float4 wB = *reinterpret_cast<const float4*>(&swgt[loc * 8 + 4]);

    const ulonglong2* p =
        reinterpret_cast<const ulonglong2*>(g_scratch) + (off.x + cg);
    int ox = off.y, oy = off.z, oz = off.w;

    unsigned long long a01 = 0ull, a23 = 0ull;   // packed (f32,f32) pairs

#define CORNER(OFF, WW) { \
    ulonglong2 v = p[OFF]; \
    unsigned long long wp; \
    asm("mov.b64 %0, {%1, %1};" : "=l"(wp) : "f"(WW)); \
    asm("fma.rn.f32x2 %0, %1, %2, %3;" : "=l"(a01) : "l"(wp), "l"(v.x), "l"(a01)); \
    asm("fma.rn.f32x2 %0, %1, %2, %3;" : "=l"(a23) : "l"(wp), "l"(v.y), "l"(a23)); }

    CORNER(0,            wA.x)
    CORNER(ox,           wA.y)
    CORNER(oy,           wA.z)
    CORNER(oy + ox,      wA.w)
    CORNER(oz,           wB.x)
    CORNER(oz + ox,      wB.y)
    CORNER(oz + oy,      wB.z)
    CORNER(oz + oy + ox, wB.w)
#undef CORNER

    float r0, r1, r2, r3;
    asm("mov.b64 {%0, %1}, %2;" : "=f"(r0), "=f"(r1) : "l"(a01));
    asm("mov.b64 {%0, %1}, %2;" : "=f"(r2), "=f"(r3) : "l"(a23));

    // stage: tile[loc][cg*4 + j]; banks (loc + 4*cg + j) distinct per warp
    int row = loc * 33 + cg * 4;
    tile[row + 0] = r0;
    tile[row + 1] = r1;
    tile[row + 2] = r2;
    tile[row + 3] = r3;
    __syncthreads();

    // coalesced writes: warp w covers channels 4w..4w+3, lane = xo
    int w    = tid >> 5;
    int lane = tid & 31;
    size_t obase = (((size_t)(n * C) * DO + zo) * HO + yo) * WO + xg * 32 + lane;
#pragma unroll
    for (int i = 0; i < 4; i++) {
        int c = w * 4 + i;
        out[obase + (size_t)c * (DO * HO * WO)] = tile[lane * 33 + c];
    }
}

extern "C" void kernel_launch(void* const* d_in, const int* in_sizes, int n_in,
                              void* d_out, int out_size) {
    const float* input = (const float*)d_in[0];
    const float* grid  = (const float*)d_in[1];
    float* out = (float*)d_out;

    transpose_cl_kernel<<<NB * (S3 / 32), dim3(32, 8)>>>(input);
    sample_kernel<<<NB * DO * HO * (WO / 32), 256>>>(grid, out);
}

// round 10
// speedup vs baseline: 1.1700x; 1.1700x over previous
#include <cuda_runtime.h>
#include <cuda_bf16.h>

// ---------------------------------------------------------------------------
// GridSample 3D, trilinear, zeros padding, align_corners=False
// input  [2, 32, 64, 64, 64] f32
// grid   [2, 96, 96, 96, 3]  f32
// output [2, 32, 96, 96, 96] f32
//
// R9 = R5 (smem-deduped coord math + packed f32x2 FMA + float4 gathers)
//   with the latency fixes the R5 metrics demanded:
//   - single __syncthreads (Phase A reads grid directly from global)
//   - __launch_bounds__(256,7): cap 36 regs -> ~87% occupancy
//   - two explicit 4-corner load batches for steady MLP
// ---------------------------------------------------------------------------

#define NB   2
#define C    32
#define D    64
#define HH   64
#define W    64
#define S3   (D * HH * W)
#define DO   96
#define HO   96
#define WO   96

// channels-last scratch: [NB][S3][C] = 64 MiB
static __device__ float g_scratch[(size_t)NB * S3 * C];

// ---------------------------------------------------------------------------
// K1: [n][c][s] -> [n][s][c] transpose, 32x32 shared tile
// ---------------------------------------------------------------------------
__global__ void transpose_cl_kernel(const float* __restrict__ in) {
    __shared__ float tile[32][33];
    int bid   = blockIdx.x;
    int n     = bid >> 13;
    int sbase = (bid & 8191) << 5;
    int tx = threadIdx.x;
    int ty = threadIdx.y;

    const float* inp = in + (size_t)n * C * S3;
#pragma unroll
    for (int i = 0; i < 4; i++) {
        int c = ty + i * 8;
        tile[c][tx] = inp[(size_t)c * S3 + sbase + tx];
    }
    __syncthreads();
    float* dst = g_scratch + (size_t)n * S3 * C;
#pragma unroll
    for (int i = 0; i < 4; i++) {
        int s = ty + i * 8;
        dst[(size_t)(sbase + s) * C + tx] = tile[tx][s];
    }
}

// ---------------------------------------------------------------------------
// K2: sampler. 256 threads, 32 locations (one 32-wide x-strip).
// Phase A (tid<32): per-location corner weights + offsets -> shared,
//                   grid coords read directly from global (one warp).
// Phase B: loc = tid>>3, cg = tid&7: 8 float4 corner gathers in two
//          4-load batches, packed f32x2 FMA accumulate, stride-33 staging,
//          coalesced writes. grid: NB*DO*HO*(WO/32) = 55296 blocks.
// ---------------------------------------------------------------------------
__global__ __launch_bounds__(256, 7) void sample_kernel(
    const float* __restrict__ grid, float* __restrict__ out) {
    __shared__ float swgt[32 * 8];       // 8 corner weights per location
    __shared__ int   soff[32 * 4];       // base4, ox, oy, oz (float4 units)
    __shared__ float tile[32 * 33];      // [loc][chan], stride 33

    int bid = blockIdx.x;
    int xg  = bid % 3;  int t = bid / 3;
    int yo  = t % HO;   t /= HO;
    int zo  = t % DO;
    int n   = t / DO;

    int tid = threadIdx.x;

    // -------- Phase A: one thread per location --------
    if (tid < 32) {
        long gbase = ((((long)n * DO + zo) * HO + yo) * WO + xg * 32 + tid) * 3;
        float gx = __ldg(grid + gbase + 0);
        float gy = __ldg(grid + gbase + 1);
        float gz = __ldg(grid + gbase + 2);

        // align_corners=False: (g+1)*32 - 0.5
        float ix = (gx + 1.0f) * 32.0f - 0.5f;
        float iy = (gy + 1.0f) * 32.0f - 0.5f;
        float iz = (gz + 1.0f) * 32.0f - 0.5f;

        float fx = floorf(ix), fy = floorf(iy), fz = floorf(iz);
        float tx = ix - fx, ty = iy - fy, tz = iz - fz;
        int x0 = (int)fx, y0 = (int)fy, z0 = (int)fz;
        int x1 = x0 + 1, y1 = y0 + 1, z1 = z0 + 1;

        float wx0 = (x0 >= 0 && x0 < W)  ? (1.0f - tx) : 0.0f;
        float wx1 = (x1 >= 0 && x1 < W)  ? tx          : 0.0f;
        float wy0 = (y0 >= 0 && y0 < HH) ? (1.0f - ty) : 0.0f;
        float wy1 = (y1 >= 0 && y1 < HH) ? ty          : 0.0f;
        float wz0 = (z0 >= 0 && z0 < D)  ? (1.0f - tz) : 0.0f;
        float wz1 = (z1 >= 0 && z1 < D)  ? tz          : 0.0f;

        int xc0 = min(max(x0, 0), W - 1),  xc1 = min(max(x1, 0), W - 1);
        int yc0 = min(max(y0, 0), HH - 1), yc1 = min(max(y1, 0), HH - 1);
        int zc0 = min(max(z0, 0), D - 1),  zc1 = min(max(z1, 0), D - 1);

        // offsets in float4 (16B) units; C floats = 8 float4
        int base4 = (((n * D + zc0) * HH + yc0) * W + xc0) * (C / 4);
        *reinterpret_cast<int4*>(&soff[tid * 4]) = make_int4(
            base4,
            (xc1 - xc0) * (C / 4),
            (yc1 - yc0) * (W * C / 4),
            (zc1 - zc0) * (HH * W * C / 4));

        float w00 = wz0 * wy0, w01 = wz0 * wy1;
        float w10 = wz1 * wy0, w11 = wz1 * wy1;
        *reinterpret_cast<float4*>(&swgt[tid * 8]) =
            make_float4(w00 * wx0, w00 * wx1, w01 * wx0, w01 * wx1);
        *reinterpret_cast<float4*>(&swgt[tid * 8 + 4]) =
            make_float4(w10 * wx0, w10 * wx1, w11 * wx0, w11 * wx1);
    }
    __syncthreads();

    // -------- Phase B: gather + packed accumulate --------
    int loc = tid >> 3;
    int cg  = tid & 7;

    int4 off = *reinterpret_cast<const int4*>(&soff[loc * 4]);   // base,ox,oy,oz
    float4 wA = *reinterpret_cast<const float4*>(&swgt[loc * 8]);
    float4 wB = *reinterpret_cast<const float4*>(&swgt[loc * 8 + 4]);

    const ulonglong2* p =
        reinterpret_cast<const ulonglong2*>(g_scratch) + (off.x + cg);
    int ox = off.y, oy = off.z, oz = off.w;

    unsigned long long a01 = 0ull, a23 = 0ull;   // packed (f32,f32) pairs

#define PKFMA(ACC, WP, VV) \
    asm("fma.rn.f32x2 %0, %1, %2, %3;" : "=l"(ACC) : "l"(WP), "l"(VV), "l"(ACC))
#define WPACK(WP, WW) \
    asm("mov.b64 %0, {%1, %1};" : "=l"(WP) : "f"(WW))

    {   // batch 1: z0 plane (4 corners in flight)
        ulonglong2 v0 = p[0];
        ulonglong2 v1 = p[ox];
        ulonglong2 v2 = p[oy];
        ulonglong2 v3 = p[oy + ox];
        unsigned long long wp;
        WPACK(wp, wA.x); PKFMA(a01, wp, v0.x); PKFMA(a23, wp, v0.y);
        WPACK(wp, wA.y); PKFMA(a01, wp, v1.x); PKFMA(a23, wp, v1.y);
        WPACK(wp, wA.z); PKFMA(a01, wp, v2.x); PKFMA(a23, wp, v2.y);
        WPACK(wp, wA.w); PKFMA(a01, wp, v3.x); PKFMA(a23, wp, v3.y);
    }
    {   // batch 2: z1 plane
        ulonglong2 v0 = p[oz];
        ulonglong2 v1 = p[oz + ox];
        ulonglong2 v2 = p[oz + oy];
        ulonglong2 v3 = p[oz + oy + ox];
        unsigned long long wp;
        WPACK(wp, wB.x); PKFMA(a01, wp, v0.x); PKFMA(a23, wp, v0.y);
        WPACK(wp, wB.y); PKFMA(a01, wp, v1.x); PKFMA(a23, wp, v1.y);
        WPACK(wp, wB.z); PKFMA(a01, wp, v2.x); PKFMA(a23, wp, v2.y);
        WPACK(wp, wB.w); PKFMA(a01, wp, v3.x); PKFMA(a23, wp, v3.y);
    }
#undef PKFMA
#undef WPACK

    float r0, r1, r2, r3;
    asm("mov.b64 {%0, %1}, %2;" : "=f"(r0), "=f"(r1) : "l"(a01));
    asm("mov.b64 {%0, %1}, %2;" : "=f"(r2), "=f"(r3) : "l"(a23));

    // stage: tile[loc][cg*4 + j]; banks (loc + 4*cg) distinct per warp
    int row = loc * 33 + cg * 4;
    tile[row + 0] = r0;
    tile[row + 1] = r1;
    tile[row + 2] = r2;
    tile[row + 3] = r3;
    __syncthreads();

    // coalesced writes: warp w covers channels 4w..4w+3, lane = xo
    int w    = tid >> 5;
    int lane = tid & 31;
    size_t obase = (((size_t)(n * C) * DO + zo) * HO + yo) * WO + xg * 32 + lane;
#pragma unroll
    for (int i = 0; i < 4; i++) {
        int c = w * 4 + i;
        out[obase + (size_t)c * (DO * HO * WO)] = tile[lane * 33 + c];
    }
}

extern "C" void kernel_launch(void* const* d_in, const int* in_sizes, int n_in,
                              void* d_out, int out_size) {
    const float* input = (const float*)d_in[0];
    const float* grid  = (const float*)d_in[1];
    float* out = (float*)d_out;

    transpose_cl_kernel<<<NB * (S3 / 32), dim3(32, 8)>>>(input);
    sample_kernel<<<NB * DO * HO * (WO / 32), 256>>>(grid, out);
}

// round 11
// speedup vs baseline: 1.1791x; 1.0078x over previous
#include <cuda_runtime.h>
#include <cuda_bf16.h>

// ---------------------------------------------------------------------------
// GridSample 3D, trilinear, zeros padding, align_corners=False
// input  [2, 32, 64, 64, 64] f32
// grid   [2, 96, 96, 96, 3]  f32
// output [2, 32, 96, 96, 96] f32
//
// R9 = R5 (smem-deduped coord math + packed f32x2 FMA + float4 gathers)
//   with the latency fixes the R5 metrics demanded:
//   - single __syncthreads (Phase A reads grid directly from global)
//   - __launch_bounds__(256,7): cap 36 regs -> ~87% occupancy
//   - two explicit 4-corner load batches for steady MLP
// ---------------------------------------------------------------------------

#define NB   2
#define C    32
#define D    64
#define HH   64
#define W    64
#define S3   (D * HH * W)
#define DO   96
#define HO   96
#define WO   96

// channels-last scratch: [NB][S3][C] = 64 MiB
static __device__ float g_scratch[(size_t)NB * S3 * C];

// ---------------------------------------------------------------------------
// K1: [n][c][s] -> [n][s][c] transpose, 32x32 shared tile
// ---------------------------------------------------------------------------
__global__ void transpose_cl_kernel(const float* __restrict__ in) {
    __shared__ float tile[32][33];
    int bid   = blockIdx.x;
    int n     = bid >> 13;
    int sbase = (bid & 8191) << 5;
    int tx = threadIdx.x;
    int ty = threadIdx.y;

    const float* inp = in + (size_t)n * C * S3;
#pragma unroll
    for (int i = 0; i < 4; i++) {
        int c = ty + i * 8;
        tile[c][tx] = inp[(size_t)c * S3 + sbase + tx];
    }
    __syncthreads();
    float* dst = g_scratch + (size_t)n * S3 * C;
#pragma unroll
    for (int i = 0; i < 4; i++) {
        int s = ty + i * 8;
        dst[(size_t)(sbase + s) * C + tx] = tile[tx][s];
    }
}

// ---------------------------------------------------------------------------
// K2: sampler. 256 threads, 32 locations (one 32-wide x-strip).
// Phase A (tid<32): per-location corner weights + offsets -> shared,
//                   grid coords read directly from global (one warp).
// Phase B: loc = tid>>3, cg = tid&7: 8 float4 corner gathers in two
//          4-load batches, packed f32x2 FMA accumulate, stride-33 staging,
//          coalesced writes. grid: NB*DO*HO*(WO/32) = 55296 blocks.
// ---------------------------------------------------------------------------
__global__ __launch_bounds__(256, 7) void sample_kernel(
    const float* __restrict__ grid, float* __restrict__ out) {
    __shared__ float swgt[32 * 8];       // 8 corner weights per location
    __shared__ int   soff[32 * 4];       // base4, ox, oy, oz (float4 units)
    __shared__ float tile[32 * 33];      // [loc][chan], stride 33

    int bid = blockIdx.x;
    int xg  = bid % 3;  int t = bid / 3;
    int yo  = t % HO;   t /= HO;
    int zo  = t % DO;
    int n   = t / DO;

    int tid = threadIdx.x;

    // -------- Phase A: one thread per location --------
    if (tid < 32) {
        long gbase = ((((long)n * DO + zo) * HO + yo) * WO + xg * 32 + tid) * 3;
        float gx = __ldg(grid + gbase + 0);
        float gy = __ldg(grid + gbase + 1);
        float gz = __ldg(grid + gbase + 2);

        // align_corners=False: (g+1)*32 - 0.5
        float ix = (gx + 1.0f) * 32.0f - 0.5f;
        float iy = (gy + 1.0f) * 32.0f - 0.5f;
        float iz = (gz + 1.0f) * 32.0f - 0.5f;

        float fx = floorf(ix), fy = floorf(iy), fz = floorf(iz);
        float tx = ix - fx, ty = iy - fy, tz = iz - fz;
        int x0 = (int)fx, y0 = (int)fy, z0 = (int)fz;
        int x1 = x0 + 1, y1 = y0 + 1, z1 = z0 + 1;

        float wx0 = (x0 >= 0 && x0 < W)  ? (1.0f - tx) : 0.0f;
        float wx1 = (x1 >= 0 && x1 < W)  ? tx          : 0.0f;
        float wy0 = (y0 >= 0 && y0 < HH) ? (1.0f - ty) : 0.0f;
        float wy1 = (y1 >= 0 && y1 < HH) ? ty          : 0.0f;
        float wz0 = (z0 >= 0 && z0 < D)  ? (1.0f - tz) : 0.0f;
        float wz1 = (z1 >= 0 && z1 < D)  ? tz          : 0.0f;

        int xc0 = min(max(x0, 0), W - 1),  xc1 = min(max(x1, 0), W - 1);
        int yc0 = min(max(y0, 0), HH - 1), yc1 = min(max(y1, 0), HH - 1);
        int zc0 = min(max(z0, 0), D - 1),  zc1 = min(max(z1, 0), D - 1);

        // offsets in float4 (16B) units; C floats = 8 float4
        int base4 = (((n * D + zc0) * HH + yc0) * W + xc0) * (C / 4);
        *reinterpret_cast<int4*>(&soff[tid * 4]) = make_int4(
            base4,
            (xc1 - xc0) * (C / 4),
            (yc1 - yc0) * (W * C / 4),
            (zc1 - zc0) * (HH * W * C / 4));

        float w00 = wz0 * wy0, w01 = wz0 * wy1;
        float w10 = wz1 * wy0, w11 = wz1 * wy1;
        *reinterpret_cast<float4*>(&swgt[tid * 8]) =
            make_float4(w00 * wx0, w00 * wx1, w01 * wx0, w01 * wx1);
        *reinterpret_cast<float4*>(&swgt[tid * 8 + 4]) =
            make_float4(w10 * wx0, w10 * wx1, w11 * wx0, w11 * wx1);
    }
    __syncthreads();

    // -------- Phase B: gather + packed accumulate --------
    int loc = tid >> 3;
    int cg  = tid & 7;

    int4 off = *reinterpret_cast<const int4*>(&soff[loc * 4]);   // base,ox,oy,oz
    float4 wA = *reinterpret_cast<const float4*>(&swgt[loc * 8]);
    float4 wB = *reinterpret_cast<const float4*>(&swgt[loc * 8 + 4]);

    const ulonglong2* p =
        reinterpret_cast<const ulonglong2*>(g_scratch) + (off.x + cg);
    int ox = off.y, oy = off.z, oz = off.w;

    unsigned long long a01 = 0ull, a23 = 0ull;   // packed (f32,f32) pairs

#define PKFMA(ACC, WP, VV) \
    asm("fma.rn.f32x2 %0, %1, %2, %3;" : "=l"(ACC) : "l"(WP), "l"(VV), "l"(ACC))
#define WPACK(WP, WW) \
    asm("mov.b64 %0, {%1, %1};" : "=l"(WP) : "f"(WW))

    {   // batch 1: z0 plane (4 corners in flight)
        ulonglong2 v0 = p[0];
        ulonglong2 v1 = p[ox];
        ulonglong2 v2 = p[oy];
        ulonglong2 v3 = p[oy + ox];
        unsigned long long wp;
        WPACK(wp, wA.x); PKFMA(a01, wp, v0.x); PKFMA(a23, wp, v0.y);
        WPACK(wp, wA.y); PKFMA(a01, wp, v1.x); PKFMA(a23, wp, v1.y);
        WPACK(wp, wA.z); PKFMA(a01, wp, v2.x); PKFMA(a23, wp, v2.y);
        WPACK(wp, wA.w); PKFMA(a01, wp, v3.x); PKFMA(a23, wp, v3.y);
    }
    {   // batch 2: z1 plane
        ulonglong2 v0 = p[oz];
        ulonglong2 v1 = p[oz + ox];
        ulonglong2 v2 = p[oz + oy];
        ulonglong2 v3 = p[oz + oy + ox];
        unsigned long long wp;
        WPACK(wp, wB.x); PKFMA(a01, wp, v0.x); PKFMA(a23, wp, v0.y);
        WPACK(wp, wB.y); PKFMA(a01, wp, v1.x); PKFMA(a23, wp, v1.y);
        WPACK(wp, wB.z); PKFMA(a01, wp, v2.x); PKFMA(a23, wp, v2.y);
        WPACK(wp, wB.w); PKFMA(a01, wp, v3.x); PKFMA(a23, wp, v3.y);
    }
#undef PKFMA
#undef WPACK

    float r0, r1, r2, r3;
    asm("mov.b64 {%0, %1}, %2;" : "=f"(r0), "=f"(r1) : "l"(a01));
    asm("mov.b64 {%0, %1}, %2;" : "=f"(r2), "=f"(r3) : "l"(a23));

    // stage: tile[loc][cg*4 + j]; banks (loc + 4*cg) distinct per warp
    int row = loc * 33 + cg * 4;
    tile[row + 0] = r0;
    tile[row + 1] = r1;
    tile[row + 2] = r2;
    tile[row + 3] = r3;
    __syncthreads();

    // coalesced writes: warp w covers channels 4w..4w+3, lane = xo
    int w    = tid >> 5;
    int lane = tid & 31;
    size_t obase = (((size_t)(n * C) * DO + zo) * HO + yo) * WO + xg * 32 + lane;
#pragma unroll
    for (int i = 0; i < 4; i++) {
        int c = w * 4 + i;
        out[obase + (size_t)c * (DO * HO * WO)] = tile[lane * 33 + c];
    }
}

extern "C" void kernel_launch(void* const* d_in, const int* in_sizes, int n_in,
                              void* d_out, int out_size) {
    const float* input = (const float*)d_in[0];
    const float* grid  = (const float*)d_in[1];
    float* out = (float*)d_out;

    transpose_cl_kernel<<<NB * (S3 / 32), dim3(32, 8)>>>(input);
    sample_kernel<<<NB * DO * HO * (WO / 32), 256>>>(grid, out);
}